// round 1
// baseline (speedup 1.0000x reference)
#include <cuda_runtime.h>
#include <cstdint>

// InformPooling: segment means over 3 time-pooled value tensors.
//   value0 [8,16384,128] ratio 1.0   -> out channels [0,128)
//   value1 [8, 8192,128] ratio 0.5   -> out channels [128,256)
//   value2 [8, 4096,256] ratio 0.25  -> out channels [256,512)
//   start/duration [8,512]
//   out [8,512,512] fp32
//
// One CTA per (query n, batch b, tensor z). 128 threads.
//  z<2 : thread t owns channel t, scalar loads (512B/row coalesced)
//  z==2: thread t owns channels {2t,2t+1} via float2 (1KB/row coalesced)
// Row loop unrolled x4 for memory-level parallelism.

#define EPS 1e-3f

__global__ __launch_bounds__(128) void inform_pool_kernel(
    const float* __restrict__ v0,
    const float* __restrict__ v1,
    const float* __restrict__ v2,
    const float* __restrict__ start,
    const float* __restrict__ dur,
    float* __restrict__ out)
{
    const int n = blockIdx.x;        // 0..511
    const int b = blockIdx.y;        // 0..7
    const int z = blockIdx.z;        // 0..2
    const int t = threadIdx.x;       // 0..127

    const float st = start[b * 512 + n];
    const float du = dur[b * 512 + n];

    float ratio; int T;
    if (z == 0)      { ratio = 1.0f;  T = 16384; }
    else if (z == 1) { ratio = 0.5f;  T = 8192;  }
    else             { ratio = 0.25f; T = 4096;  }

    int s = (int)floorf(st * ratio);
    if (s > T - 1) s = T - 1;
    int e = (int)ceilf((st + du + EPS) * ratio);
    if (e > T - 1) e = T - 1;

    const int cnt = e - s;
    const float inv = (cnt > 0) ? (1.0f / (float)cnt) : 0.0f;

    float* orow = out + ((size_t)b * 512 + n) * 512;

    if (z < 2) {
        const float* src = (z == 0) ? v0 : v1;
        const int coff   = (z == 0) ? 0 : 128;
        const float* p = src + ((size_t)b * T + s) * 128 + t;

        float a0 = 0.f, a1 = 0.f, a2 = 0.f, a3 = 0.f;
        int r = 0;
        const int c4 = (cnt > 0) ? (cnt & ~3) : 0;
        for (; r < c4; r += 4) {
            a0 += p[0];
            a1 += p[128];
            a2 += p[256];
            a3 += p[384];
            p += 512;
        }
        for (; r < cnt; ++r) { a0 += *p; p += 128; }
        float acc = (a0 + a1) + (a2 + a3);
        orow[coff + t] = acc * inv;
    } else {
        // v2: 256 channels, float2 per thread
        const float2* p = (const float2*)(v2 + ((size_t)b * T + s) * 256) + t;
        float2 a0 = {0.f, 0.f}, a1 = {0.f, 0.f}, a2 = {0.f, 0.f}, a3 = {0.f, 0.f};
        int r = 0;
        const int c4 = (cnt > 0) ? (cnt & ~3) : 0;
        for (; r < c4; r += 4) {
            float2 x0 = p[0];
            float2 x1 = p[128];
            float2 x2 = p[256];
            float2 x3 = p[384];
            a0.x += x0.x; a0.y += x0.y;
            a1.x += x1.x; a1.y += x1.y;
            a2.x += x2.x; a2.y += x2.y;
            a3.x += x3.x; a3.y += x3.y;
            p += 512;
        }
        for (; r < cnt; ++r) {
            float2 x = *p;
            a0.x += x.x; a0.y += x.y;
            p += 128;
        }
        float ax = (a0.x + a1.x) + (a2.x + a3.x);
        float ay = (a0.y + a1.y) + (a2.y + a3.y);
        orow[256 + 2 * t]     = ax * inv;
        orow[256 + 2 * t + 1] = ay * inv;
    }
}

extern "C" void kernel_launch(void* const* d_in, const int* in_sizes, int n_in,
                              void* d_out, int out_size)
{
    const float* v0    = (const float*)d_in[0];
    const float* v1    = (const float*)d_in[1];
    const float* v2    = (const float*)d_in[2];
    const float* start = (const float*)d_in[3];
    const float* dur   = (const float*)d_in[4];
    float* out = (float*)d_out;

    dim3 grid(512, 8, 3);
    inform_pool_kernel<<<grid, 128>>>(v0, v1, v2, start, dur, out);
}

// round 9
// speedup vs baseline: 1.1240x; 1.1240x over previous
#include <cuda_runtime.h>
#include <cstdint>

// InformPooling: segment means over 3 time-pooled value tensors.
//   value0 [8,16384,128] ratio 1.0   -> out ch [0,128)
//   value1 [8, 8192,128] ratio 0.5   -> out ch [128,256)
//   value2 [8, 4096,256] ratio 0.25  -> out ch [256,512)
//   start/duration [8,512] ; out [8,512,512] fp32
//
// One CTA per (query, batch, tensor). 128 threads, float4 loads:
//   z<2 : 32 float4/row; threads split as (rowgroup = t>>5, f4 = t&31),
//         4 rows per step, unrolled x4 (16 rows / 8KB in flight per CTA).
//   z==2: 64 float4/row; (rowgroup = t>>6, f4 = t&63), 2 rows/step, x4.
// Smem reduction folds rowgroup partials, vectorized float4 store.

#define EPS 1e-3f

__device__ __forceinline__ void f4add(float4& a, const float4 b) {
    a.x += b.x; a.y += b.y; a.z += b.z; a.w += b.w;
}

__global__ __launch_bounds__(128) void inform_pool_kernel(
    const float* __restrict__ v0,
    const float* __restrict__ v1,
    const float* __restrict__ v2,
    const float* __restrict__ start,
    const float* __restrict__ dur,
    float* __restrict__ out)
{
    const int n = blockIdx.x;        // 0..511
    const int b = blockIdx.y;        // 0..7
    const int z = blockIdx.z;        // 0..2
    const int t = threadIdx.x;       // 0..127

    __shared__ float4 red[128];

    const float st = start[b * 512 + n];
    const float du = dur[b * 512 + n];

    float ratio; int T;
    if (z == 0)      { ratio = 1.0f;  T = 16384; }
    else if (z == 1) { ratio = 0.5f;  T = 8192;  }
    else             { ratio = 0.25f; T = 4096;  }

    int s = (int)floorf(st * ratio);
    if (s > T - 1) s = T - 1;
    int e = (int)ceilf((st + du + EPS) * ratio);
    if (e > T - 1) e = T - 1;

    const int rows = e - s;
    const float inv = (rows > 0) ? (1.0f / (float)rows) : 0.0f;

    float* orow = out + ((size_t)b * 512 + n) * 512;

    if (z < 2) {
        const float* src = (z == 0) ? v0 : v1;
        const int coff   = (z == 0) ? 0 : 128;
        const float4* base = (const float4*)(src + ((size_t)b * T + s) * 128);
        const int rg = t >> 5;       // 0..3
        const int f4 = t & 31;       // 0..31

        float4 a0 = {0,0,0,0}, a1 = {0,0,0,0}, a2 = {0,0,0,0}, a3 = {0,0,0,0};
        const int full = rows >> 2;          // complete 4-row groups
        const float4* p = base + rg * 32 + f4;

        int g = 0;
        for (; g + 4 <= full; g += 4) {      // 16 rows per iter
            float4 x0 = p[0];
            float4 x1 = p[128];
            float4 x2 = p[256];
            float4 x3 = p[384];
            f4add(a0, x0); f4add(a1, x1); f4add(a2, x2); f4add(a3, x3);
            p += 512;
        }
        for (; g < full; ++g) { float4 x = p[0]; f4add(a0, x); p += 128; }
        const int tail = rows & 3;
        if (rg < tail) {                     // rows full*4 .. full*4+tail-1
            float4 x = base[(full * 4 + rg) * 32 + f4];
            f4add(a1, x);
        }
        f4add(a0, a1); f4add(a2, a3); f4add(a0, a2);

        red[t] = a0;
        __syncthreads();
        if (t < 32) {
            float4 r0 = red[t], r1 = red[t + 32], r2 = red[t + 64], r3 = red[t + 96];
            f4add(r0, r1); f4add(r2, r3); f4add(r0, r2);
            r0.x *= inv; r0.y *= inv; r0.z *= inv; r0.w *= inv;
            ((float4*)(orow + coff))[t] = r0;
        }
    } else {
        const float4* base = (const float4*)(v2 + ((size_t)b * T + s) * 256);
        const int rg = t >> 6;       // 0..1
        const int f4 = t & 63;       // 0..63

        float4 a0 = {0,0,0,0}, a1 = {0,0,0,0}, a2 = {0,0,0,0}, a3 = {0,0,0,0};
        const int full = rows >> 1;          // complete 2-row groups
        const float4* p = base + rg * 64 + f4;

        int g = 0;
        for (; g + 4 <= full; g += 4) {      // 8 rows per iter
            float4 x0 = p[0];
            float4 x1 = p[128];
            float4 x2 = p[256];
            float4 x3 = p[384];
            f4add(a0, x0); f4add(a1, x1); f4add(a2, x2); f4add(a3, x3);
            p += 512;
        }
        for (; g < full; ++g) { float4 x = p[0]; f4add(a0, x); p += 128; }
        const int tail = rows & 1;
        if (rg < tail) {
            float4 x = base[(full * 2 + rg) * 64 + f4];
            f4add(a1, x);
        }
        f4add(a0, a1); f4add(a2, a3); f4add(a0, a2);

        red[t] = a0;
        __syncthreads();
        if (t < 64) {
            float4 r0 = red[t], r1 = red[t + 64];
            f4add(r0, r1);
            r0.x *= inv; r0.y *= inv; r0.z *= inv; r0.w *= inv;
            ((float4*)(orow + 256))[t] = r0;
        }
    }
}

extern "C" void kernel_launch(void* const* d_in, const int* in_sizes, int n_in,
                              void* d_out, int out_size)
{
    const float* v0    = (const float*)d_in[0];
    const float* v1    = (const float*)d_in[1];
    const float* v2    = (const float*)d_in[2];
    const float* start = (const float*)d_in[3];
    const float* dur   = (const float*)d_in[4];
    float* out = (float*)d_out;

    dim3 grid(512, 8, 3);
    inform_pool_kernel<<<grid, 128>>>(v0, v1, v2, start, dur, out);
}